// round 14
// baseline (speedup 1.0000x reference)
#include <cuda_runtime.h>
#include <cuda_bf16.h>

// Block partial sums for the MSE reduction. 8192 slots >> max blocks used.
__device__ double g_partials[8192];

// ---------------------------------------------------------------------------
// Kernel 1: per-(b,t) column reduction over f of (o - t), square, block-reduce.
//   o, t point at channel-0 of [B, 2, F, T] tensors.
//   Thread id -> (b, t); loads strided by T (coalesced across threads in t).
// ---------------------------------------------------------------------------
template <int F, int T>
__global__ void __launch_bounds__(256)
mse_cols_kernel(const float* __restrict__ o,
                const float* __restrict__ t,
                int BT)
{
    int id = blockIdx.x * blockDim.x + threadIdx.x;
    float d = 0.0f;
    if (id < BT) {
        int b  = id / T;
        int tt = id - b * T;
        size_t base = (size_t)b * (size_t)(2 * F) * (size_t)T + (size_t)tt;
        const float* op = o + base;
        const float* tp = t + base;
        float s0 = 0.f, s1 = 0.f, s2 = 0.f, s3 = 0.f;
#pragma unroll
        for (int f = 0; f < F; f += 4) {
            s0 += op[(size_t)(f + 0) * T] - tp[(size_t)(f + 0) * T];
            s1 += op[(size_t)(f + 1) * T] - tp[(size_t)(f + 1) * T];
            s2 += op[(size_t)(f + 2) * T] - tp[(size_t)(f + 2) * T];
            s3 += op[(size_t)(f + 3) * T] - tp[(size_t)(f + 3) * T];
        }
        d = (s0 + s1) + (s2 + s3);
    }
    double v = (double)d * (double)d;

    // block reduce (double)
    __shared__ double sh[8];
    int lane = threadIdx.x & 31;
    int w    = threadIdx.x >> 5;
#pragma unroll
    for (int off = 16; off; off >>= 1)
        v += __shfl_down_sync(0xffffffffu, v, off);
    if (lane == 0) sh[w] = v;
    __syncthreads();
    if (w == 0) {
        v = (lane < 8) ? sh[lane] : 0.0;
#pragma unroll
        for (int off = 4; off; off >>= 1)
            v += __shfl_down_sync(0xffffffffu, v, off);
        if (lane == 0) g_partials[blockIdx.x] = v;
    }
}

// Generic (runtime F/T) fallback — same structure.
__global__ void __launch_bounds__(256)
mse_cols_kernel_gen(const float* __restrict__ o,
                    const float* __restrict__ t,
                    int F, int T, int BT)
{
    int id = blockIdx.x * blockDim.x + threadIdx.x;
    float d = 0.0f;
    if (id < BT) {
        int b  = id / T;
        int tt = id - b * T;
        size_t base = (size_t)b * (size_t)(2 * F) * (size_t)T + (size_t)tt;
        const float* op = o + base;
        const float* tp = t + base;
        float s = 0.f;
#pragma unroll 4
        for (int f = 0; f < F; f++)
            s += op[(size_t)f * T] - tp[(size_t)f * T];
        d = s;
    }
    double v = (double)d * (double)d;

    __shared__ double sh[8];
    int lane = threadIdx.x & 31;
    int w    = threadIdx.x >> 5;
#pragma unroll
    for (int off = 16; off; off >>= 1)
        v += __shfl_down_sync(0xffffffffu, v, off);
    if (lane == 0) sh[w] = v;
    __syncthreads();
    if (w == 0) {
        v = (lane < 8) ? sh[lane] : 0.0;
#pragma unroll
        for (int off = 4; off; off >>= 1)
            v += __shfl_down_sync(0xffffffffu, v, off);
        if (lane == 0) g_partials[blockIdx.x] = v;
    }
}

// ---------------------------------------------------------------------------
// Kernel 2: single block. KLD + cross-entropy + partial-sum + weighted combine.
// ---------------------------------------------------------------------------
__device__ __forceinline__ double block_sum_256(double v)
{
    __shared__ double sh[8];
    int lane = threadIdx.x & 31;
    int w    = threadIdx.x >> 5;
#pragma unroll
    for (int off = 16; off; off >>= 1)
        v += __shfl_down_sync(0xffffffffu, v, off);
    if (lane == 0) sh[w] = v;
    __syncthreads();
    double r = 0.0;
    if (w == 0) {
        r = (lane < 8) ? sh[lane] : 0.0;
#pragma unroll
        for (int off = 4; off; off >>= 1)
            r += __shfl_down_sync(0xffffffffu, r, off);
    }
    __syncthreads();
    return r;  // valid on thread 0
}

__global__ void __launch_bounds__(256)
finalize_kernel(const float* __restrict__ mean,
                const float* __restrict__ log_var,
                const float* __restrict__ oclas,
                const long long* __restrict__ tclas,
                const float* __restrict__ weight,
                int B, int Z, int C, int nPartials,
                float* __restrict__ out)
{
    int tid = threadIdx.x;

    // --- KLD: sum(1 + lv - m^2 - exp(lv)) ---
    double kacc = 0.0;
    int n = B * Z;
    for (int i = tid; i < n; i += blockDim.x) {
        float lv = log_var[i];
        float m  = mean[i];
        kacc += (double)(1.0f + lv - m * m - expf(lv));
    }
    double kld_sum = block_sum_256(kacc);

    // --- Cross-entropy: mean_b of -(logit[tgt] - max - log(sumexp)) ---
    double cacc = 0.0;
    for (int b = tid; b < B; b += blockDim.x) {
        const float* row = oclas + (size_t)b * C;
        float mx = row[0];
        for (int j = 1; j < C; j++) mx = fmaxf(mx, row[j]);
        float se = 0.f;
        for (int j = 0; j < C; j++) se += expf(row[j] - mx);
        int tg = (int)tclas[b];
        if (tg < 0) tg = 0;
        if (tg >= C) tg = C - 1;
        cacc += (double)(-(row[tg] - mx - logf(se)));
    }
    double ce_sum = block_sum_256(cacc);

    // --- MSE partials ---
    double macc = 0.0;
    for (int i = tid; i < nPartials; i += blockDim.x)
        macc += g_partials[i];
    double mse_sum = block_sum_256(macc);

    if (tid == 0) {
        float w0 = weight[0], w1 = weight[1], w2 = weight[2];
        double mse  = 4.0 * mse_sum;                 // ISSQ_SCALE=2 -> factor 4
        double kld  = -0.5 * kld_sum;
        double clas = ce_sum / (double)B;
        out[0] = (float)((double)w0 * mse + (double)w1 * kld + (double)w2 * clas);
    }
}

// ---------------------------------------------------------------------------
// Launch
// ---------------------------------------------------------------------------
extern "C" void kernel_launch(void* const* d_in, const int* in_sizes, int n_in,
                              void* d_out, int out_size)
{
    const float*     mean     = (const float*)d_in[0];       // [B, Z]
    const float*     log_var  = (const float*)d_in[1];       // [B, Z]
    const float*     orec     = (const float*)d_in[2];       // [B, 2, F, T]
    const float*     oclas    = (const float*)d_in[3];       // [B, C]
    const float*     trec     = (const float*)d_in[4];       // [B, 2, F, T]
    const long long* tclas    = (const long long*)d_in[5];   // [B] int64
    // batch_size / img_size scalars (if present) ignored; weight is last input.
    const float*     weight   = (const float*)d_in[n_in - 1]; // [3]

    int B  = in_sizes[5];
    int Z  = in_sizes[0] / B;
    int C  = in_sizes[3] / B;
    int FT = in_sizes[2] / (2 * B);   // F * T

    const int THREADS = 256;

    if (FT == 128 * 2048) {
        constexpr int F = 128, T = 2048;
        int BT = B * T;
        int nBlocks = (BT + THREADS - 1) / THREADS;   // 512 for B=64
        mse_cols_kernel<F, T><<<nBlocks, THREADS>>>(orec, trec, BT);
        finalize_kernel<<<1, THREADS>>>(mean, log_var, oclas, tclas, weight,
                                        B, Z, C, nBlocks, (float*)d_out);
    } else {
        // Fallback: assume T = 2048 (img_size in this problem), derive F.
        int T = 2048;
        int F = FT / T;
        if (F * T != FT) { F = FT; T = 1; }  // degenerate safety
        int BT = B * T;
        int nBlocks = (BT + THREADS - 1) / THREADS;
        if (nBlocks > 8192) nBlocks = 8192;  // clamp to scratch (not expected)
        mse_cols_kernel_gen<<<nBlocks, THREADS>>>(orec, trec, F, T, BT);
        finalize_kernel<<<1, THREADS>>>(mean, log_var, oclas, tclas, weight,
                                        B, Z, C, nBlocks, (float*)d_out);
    }
}